// round 5
// baseline (speedup 1.0000x reference)
#include <cuda_runtime.h>
#include <math.h>

#define NNODES 50000
#define NEDGES 800000
#define NGRAPH 512
#define MAXF   512

// ---- scratch (device globals; no allocation allowed) ----
__device__ float g_hs[NNODES * MAXF];       // h * dis (pre-scaled gemm output)
__device__ float g_x [NNODES * MAXF];       // activations after aggregate+relu
__device__ int   g_deg[NNODES];             // in-degree (without self loop)
__device__ float g_dis[NNODES];             // rsqrt(deg+1)
__device__ int   g_rowstart[NNODES];
__device__ int   g_cursor[NNODES];
__device__ int   g_csr[NEDGES];             // src node per CSR slot (grouped by dst)
__device__ float g_wgate[NNODES];
__device__ float g_feats[NGRAPH * 1024];    // [ws(512) | max(512)] per graph
__device__ int   g_tsum[1024];
__device__ int   g_gstart[NGRAPH + 1];

// ---- graph structure build ----
__global__ void k_zero() {
    for (int i = blockIdx.x * blockDim.x + threadIdx.x; i < NNODES;
         i += gridDim.x * blockDim.x) {
        g_deg[i] = 0;
        g_cursor[i] = 0;
    }
}

__global__ void k_deg(const int* __restrict__ ei) {
    for (int e = blockIdx.x * blockDim.x + threadIdx.x; e < NEDGES;
         e += gridDim.x * blockDim.x) {
        int d = ei[NEDGES + e];
        if (d >= 0 && d < NNODES) atomicAdd(&g_deg[d], 1);
    }
}

__global__ void k_dis() {
    int n = blockIdx.x * blockDim.x + threadIdx.x;
    if (n < NNODES) g_dis[n] = rsqrtf((float)(g_deg[n] + 1));
}

// 3-phase exclusive scan of g_deg -> g_rowstart (1024 logical threads)
__global__ void k_scan1() {
    int t = blockIdx.x * blockDim.x + threadIdx.x;   // 4 blocks * 256
    const int chunk = (NNODES + 1023) / 1024;
    int base = t * chunk, s = 0;
    for (int i = 0; i < chunk; i++) {
        int n = base + i;
        if (n < NNODES) s += g_deg[n];
    }
    g_tsum[t] = s;
}
__global__ void k_scan2() {  // 1 block, 1024 threads
    __shared__ int sh[1024];
    int t = threadIdx.x;
    sh[t] = g_tsum[t];
    __syncthreads();
    for (int off = 1; off < 1024; off <<= 1) {
        int v = (t >= off) ? sh[t - off] : 0;
        __syncthreads();
        sh[t] += v;
        __syncthreads();
    }
    g_tsum[t] = (t == 0) ? 0 : sh[t - 1];
}
__global__ void k_scan3() {
    int t = blockIdx.x * blockDim.x + threadIdx.x;
    const int chunk = (NNODES + 1023) / 1024;
    int base = t * chunk, off = g_tsum[t];
    for (int i = 0; i < chunk; i++) {
        int n = base + i;
        if (n < NNODES) {
            g_rowstart[n] = off;
            off += g_deg[n];
        }
    }
}

__global__ void k_csr(const int* __restrict__ ei) {
    for (int e = blockIdx.x * blockDim.x + threadIdx.x; e < NEDGES;
         e += gridDim.x * blockDim.x) {
        int s = ei[e];
        int d = ei[NEDGES + e];
        if (s < 0 || s >= NNODES || d < 0 || d >= NNODES) continue;
        int pos = g_rowstart[d] + atomicAdd(&g_cursor[d], 1);
        if (pos >= 0 && pos < NEDGES) g_csr[pos] = s;
    }
}

// ---- GEMM: C = A(MxK) @ B(KxN)
// EPI 0: C = (A@B) * dis[row]          (pre-scale for aggregation)
// EPI 1: C = relu(A@B + bias[col])     (head)
// ASEL: 0 = Aarg, 1 = g_x, 2 = g_feats
// CSEL: 0 = Carg, 1 = g_hs
template <int BM, int BN, int BK, int TM, int TN, int EPI, int ASEL, int CSEL>
__global__ void k_gemm(const float* __restrict__ Aarg,
                       const float* __restrict__ B,
                       float* __restrict__ Carg, int M, int Nn, int K,
                       const float* __restrict__ bias) {
    const float* __restrict__ A =
        (ASEL == 0) ? Aarg : (ASEL == 1) ? (const float*)g_x : (const float*)g_feats;
    float* __restrict__ C = (CSEL == 0) ? Carg : (float*)g_hs;

    __shared__ float As[BK][BM + 4];
    __shared__ float Bs[BK][BN + 4];
    const int tid = threadIdx.x;              // 256 threads
    const int tx = tid % (BN / TN);
    const int ty = tid / (BN / TN);
    const int bm = blockIdx.x * BM;
    const int bn = blockIdx.y * BN;

    float acc[TM][TN];
#pragma unroll
    for (int i = 0; i < TM; i++)
#pragma unroll
        for (int j = 0; j < TN; j++) acc[i][j] = 0.f;

    for (int k0 = 0; k0 < K; k0 += BK) {
#pragma unroll
        for (int i = 0; i < (BM * BK / 4) / 256; i++) {
            int idx = tid + i * 256;
            int r = idx / (BK / 4), c = idx % (BK / 4);
            int row = bm + r;
            float4 v = (row < M)
                ? *(const float4*)&A[(size_t)row * K + k0 + c * 4]
                : make_float4(0.f, 0.f, 0.f, 0.f);
            As[c * 4 + 0][r] = v.x;
            As[c * 4 + 1][r] = v.y;
            As[c * 4 + 2][r] = v.z;
            As[c * 4 + 3][r] = v.w;
        }
#pragma unroll
        for (int i = 0; i < (BK * BN / 4) / 256; i++) {
            int idx = tid + i * 256;
            int r = idx / (BN / 4), c = idx % (BN / 4);
            float4 v = *(const float4*)&B[(size_t)(k0 + r) * Nn + bn + c * 4];
            *(float4*)&Bs[r][c * 4] = v;
        }
        __syncthreads();
#pragma unroll
        for (int kk = 0; kk < BK; kk++) {
            float ra[TM], rb[TN];
#pragma unroll
            for (int i = 0; i < TM; i++) ra[i] = As[kk][ty * TM + i];
#pragma unroll
            for (int j = 0; j < TN; j++) rb[j] = Bs[kk][tx * TN + j];
#pragma unroll
            for (int i = 0; i < TM; i++)
#pragma unroll
                for (int j = 0; j < TN; j++) acc[i][j] += ra[i] * rb[j];
        }
        __syncthreads();
    }

#pragma unroll
    for (int i = 0; i < TM; i++) {
        int row = bm + ty * TM + i;
        if (row >= M) continue;
        float scale = (EPI == 0) ? g_dis[row] : 1.f;
#pragma unroll
        for (int j = 0; j < TN; j++) {
            int col = bn + tx * TN + j;
            float v = acc[i][j];
            if (EPI == 0)
                v *= scale;
            else
                v = fmaxf(v + bias[col], 0.f);
            C[(size_t)row * Nn + col] = v;
        }
    }
}

// ---- aggregation: x[d] = relu(dis[d]*(hs[d] + sum_{s->d} hs[s]) + b) ----
template <int F>
__global__ void k_agg(const float* __restrict__ bias) {
    int d = blockIdx.x;
    int f = threadIdx.x;  // 256
    float dd = g_dis[d];
    float acc0 = g_hs[(size_t)d * F + f];
    float acc1 = (F == 512) ? g_hs[(size_t)d * F + f + 256] : 0.f;
    int s0 = g_rowstart[d], cnt = g_deg[d];
    for (int j = 0; j < cnt; j++) {
        int s = g_csr[s0 + j];
        acc0 += g_hs[(size_t)s * F + f];
        if (F == 512) acc1 += g_hs[(size_t)s * F + f + 256];
    }
    g_x[(size_t)d * F + f] = fmaxf(acc0 * dd + bias[f], 0.f);
    if (F == 512)
        g_x[(size_t)d * F + f + 256] = fmaxf(acc1 * dd + bias[f + 256], 0.f);
}

// ---- pooling ----
__global__ void k_gate(const float* __restrict__ pw, const float* __restrict__ pb) {
    int warp = (blockIdx.x * blockDim.x + threadIdx.x) >> 5;
    int lane = threadIdx.x & 31;
    if (warp >= NNODES) return;
    const float* row = &g_x[(size_t)warp * 512];
    float s = 0.f;
#pragma unroll 4
    for (int i = lane; i < 512; i += 32) s += row[i] * pw[i];
#pragma unroll
    for (int o = 16; o; o >>= 1) s += __shfl_xor_sync(0xFFFFFFFFu, s, o);
    if (lane == 0) g_wgate[warp] = 1.f / (1.f + expf(-(s + pb[0])));
}

__global__ void k_gstart(const int* __restrict__ batch) {
    for (int n = blockIdx.x * blockDim.x + threadIdx.x; n < NNODES;
         n += gridDim.x * blockDim.x) {
        int b = batch[n];
        if (b < 0) b = 0;
        if (b >= NGRAPH) b = NGRAPH - 1;
        int prev = -1;
        if (n) {
            prev = batch[n - 1];
            if (prev < 0) prev = 0;
            if (prev >= NGRAPH) prev = NGRAPH - 1;
        }
        for (int g = prev + 1; g <= b; g++) g_gstart[g] = n;
        if (n == NNODES - 1)
            for (int g = b + 1; g <= NGRAPH; g++) g_gstart[g] = NNODES;
    }
}

__global__ void k_pool() {
    int g = blockIdx.x;       // 512 blocks
    int f = threadIdx.x;      // 256 threads
    int s = g_gstart[g], e = g_gstart[g + 1];
    float ws0 = 0.f, ws1 = 0.f, mx0 = 0.f, mx1 = 0.f;
    for (int n = s; n < e; n++) {
        float w = g_wgate[n];
        float v0 = g_x[(size_t)n * 512 + f];
        float v1 = g_x[(size_t)n * 512 + f + 256];
        ws0 += v0 * w;
        ws1 += v1 * w;
        mx0 = fmaxf(mx0, v0);
        mx1 = fmaxf(mx1, v1);
    }
    g_feats[g * 1024 + f]       = ws0;
    g_feats[g * 1024 + f + 256] = ws1;
    g_feats[g * 1024 + 512 + f] = mx0;
    g_feats[g * 1024 + 768 + f] = mx1;
}

extern "C" void kernel_launch(void* const* d_in, const int* in_sizes, int n_in,
                              void* d_out, int out_size) {
    const float* xin   = (const float*)d_in[0];
    const int*   ei    = (const int*)d_in[1];    // int32 per harness metadata
    const int*   batch = (const int*)d_in[2];    // int32 per harness metadata
    const float* W1 = (const float*)d_in[3];
    const float* b1 = (const float*)d_in[4];
    const float* W2 = (const float*)d_in[5];
    const float* b2 = (const float*)d_in[6];
    const float* W3 = (const float*)d_in[7];
    const float* b3 = (const float*)d_in[8];
    const float* pw = (const float*)d_in[9];
    const float* pb = (const float*)d_in[10];
    const float* Wo = (const float*)d_in[11];
    const float* bo = (const float*)d_in[12];
    float* out = (float*)d_out;

    // graph structure (pure kernel launches; graph-capturable)
    k_zero<<<196, 256>>>();
    k_deg<<<512, 256>>>(ei);
    k_dis<<<(NNODES + 255) / 256, 256>>>();
    k_scan1<<<4, 256>>>();
    k_scan2<<<1, 1024>>>();
    k_scan3<<<4, 256>>>();
    k_csr<<<512, 256>>>(ei);

    const int MBLK = (NNODES + 127) / 128;  // 391

    // layer 1: [N,256]@[256,256] -> g_hs (A = xin)
    k_gemm<128, 128, 16, 8, 8, 0, 0, 1><<<dim3(MBLK, 2), 256>>>(
        xin, W1, nullptr, NNODES, 256, 256, nullptr);
    k_agg<256><<<NNODES, 256>>>(b1);

    // layer 2: [N,256]@[256,256] -> g_hs (A = g_x)
    k_gemm<128, 128, 16, 8, 8, 0, 1, 1><<<dim3(MBLK, 2), 256>>>(
        nullptr, W2, nullptr, NNODES, 256, 256, nullptr);
    k_agg<256><<<NNODES, 256>>>(b2);

    // layer 3: [N,256]@[256,512] -> g_hs (A = g_x)
    k_gemm<128, 128, 16, 8, 8, 0, 1, 1><<<dim3(MBLK, 4), 256>>>(
        nullptr, W3, nullptr, NNODES, 512, 256, nullptr);
    k_agg<512><<<NNODES, 256>>>(b3);

    // pooling
    k_gate<<<(NNODES + 7) / 8, 256>>>(pw, pb);
    k_gstart<<<196, 256>>>(batch);
    k_pool<<<NGRAPH, 256>>>();

    // head: [512,1024]@[1024,2048] + bias, relu (A = g_feats, C = out)
    k_gemm<64, 64, 16, 4, 4, 1, 2, 0><<<dim3(8, 32), 256>>>(
        nullptr, Wo, out, NGRAPH, 2048, 1024, bo);
}